// round 10
// baseline (speedup 1.0000x reference)
#include <cuda_runtime.h>
#include <cuda_fp16.h>

typedef unsigned long long u64;
typedef unsigned int u32;

#define NA 8192
#define NB 8192
#define NLAYERS 16
#define SIGMA_U 33554432.0f   // 2^25
#define NBLOCKS 512

// ---------------- static device scratch (no allocation) ----------------
__device__ __align__(128) unsigned char d_M[(size_t)NA * NB]; // A-tiled uf8, 64 MB
__device__ float d_u[NA];
__device__ float d_v[NB];
__device__ __half d_u16[NA];
__device__ __half d_v16[NB];
__device__ int d_barcnt;                 // global barrier arrival counter
__device__ volatile unsigned d_barphase; // global barrier phase (monotonic per run)

// ---------------- packed f32x2 helpers (encode only) ----------------
__device__ __forceinline__ u64 fma2(u64 a, u64 b, u64 c) {
    u64 d;
    asm("fma.rn.f32x2 %0,%1,%2,%3;" : "=l"(d) : "l"(a), "l"(b), "l"(c));
    return d;
}
__device__ __forceinline__ u64 add2(u64 a, u64 b) {
    u64 d;
    asm("add.rn.f32x2 %0,%1,%2;" : "=l"(d) : "l"(a), "l"(b));
    return d;
}
__device__ __forceinline__ u64 mul2(u64 a, u64 b) {
    u64 d;
    asm("mul.rn.f32x2 %0,%1,%2;" : "=l"(d) : "l"(a), "l"(b));
    return d;
}
__device__ __forceinline__ u64 pack2(float x) {
    u64 d;
    asm("mov.b64 %0, {%1, %1};" : "=l"(d) : "f"(x));
    return d;
}

#define MAG2  0x4B4000004B400000ull
#define NMAG2 0xCB400000CB400000ull
#define NONE2 0xBF800000BF800000ull

struct EC { u64 p5, p4, p3, p2, p1, p0; };
__device__ __forceinline__ EC make_ec() {
    EC e;
    e.p5 = pack2(1.33335581465e-3f);
    e.p4 = pack2(9.61812910763e-3f);
    e.p3 = pack2(5.55041086648e-2f);
    e.p2 = pack2(2.40226506959e-1f);
    e.p1 = pack2(6.93147180560e-1f);
    e.p0 = pack2(1.0f);
    return e;
}

// encode a packed pair of C values -> two uf8 bytes (b0 | b1<<8), MUFU-free.
__device__ __forceinline__ u32 enc2(u64 cpair, u64 negk2, const EC& ec) {
    u64 p = mul2(cpair, negk2);
    u64 t = add2(p, MAG2);
    u64 uu = add2(t, NMAG2);
    u64 fr = fma2(uu, NONE2, p);
    u64 r = fma2(ec.p5, fr, ec.p4);
    r = fma2(r, fr, ec.p3);
    r = fma2(r, fr, ec.p2);
    r = fma2(r, fr, ec.p1);
    r = fma2(r, fr, ec.p0);
    u32 tl = (u32)t, th = (u32)(t >> 32);
    u32 rl = (u32)r, rh = (u32)(r >> 32);
    u32 b0 = ((tl << 23) + rl + 0xC8040000u) >> 19;
    u32 b1 = ((th << 23) + rh + 0xC8040000u) >> 19;
    return b0 | (b1 << 8);
}

// ---------------- encode: C -> uf8, permuted into mma A-tiles --------------
// Tile = 16x16 uf8 (256B). Byte (lane, q) of a tile holds
//   A[lane/4 + 8*((q>>1)&1)][(lane%4)*2 + (q&1) + 8*(q>>2)]
// so one LDG.64 per lane yields mma A-fragment regs a0..a3 after (byte<<6)
// f16 expansion (uf8 bias 15 == f16 bias -> exact decode).
__global__ void __launch_bounds__(256) encode_kernel(const float* __restrict__ C,
                                                     const float* __restrict__ epsp) {
    __shared__ unsigned char sm[64][68];
    const float eps = __ldg(epsp);
    const u64 negk2 = pack2(-1.0f / (eps * 0.69314718056f));
    const EC ec = make_ec();
    const int t = threadIdx.x;
    const int i0 = blockIdx.y * 64, j0 = blockIdx.x * 64;

    {   // init v = 1
        int gid = (blockIdx.y * gridDim.x + blockIdx.x) * 256 + t;
        if (gid < NB) { d_v16[gid] = __float2half(1.0f); d_v[gid] = 1.0f; }
    }

    // load 64x64 C tile, encode to uf8 in smem
    int r = t >> 2, c0 = (t & 3) * 16;
    const float4* Crow = (const float4*)(C + (size_t)(i0 + r) * NB + j0 + c0);
    u32* srow = (u32*)&sm[r][c0];
#pragma unroll
    for (int q = 0; q < 4; ++q) {
        float4 f = Crow[q];
        u64 p0, p1;
        asm("mov.b64 %0,{%1,%2};" : "=l"(p0) : "f"(f.x), "f"(f.y));
        asm("mov.b64 %0,{%1,%2};" : "=l"(p1) : "f"(f.z), "f"(f.w));
        srow[q] = enc2(p0, negk2, ec) | (enc2(p1, negk2, ec) << 16);
    }
    __syncthreads();

    // write 16 A-subtiles (8 warps x 2 iterations)
    const int lane = t & 31, wid = t >> 5;
#pragma unroll
    for (int sub = wid; sub < 16; sub += 8) {
        int a = sub >> 2, b = sub & 3;
        u32 lo = 0, hi = 0;
#pragma unroll
        for (int q = 0; q < 8; ++q) {
            int R = (lane >> 2) + 8 * ((q >> 1) & 1);
            int k = (lane & 3) * 2 + (q & 1) + 8 * (q >> 2);
            u32 byte = sm[a * 16 + R][b * 16 + k];
            if (q < 4) lo |= byte << (8 * q); else hi |= byte << (8 * (q - 4));
        }
        size_t off = (size_t)(i0 / 16 + a) * 131072 + (size_t)(j0 / 16 + b) * 256 + lane * 8;
        *(uint2*)(d_M + off) = make_uint2(lo, hi);
    }
}

// ---------------- mma + movmatrix wrappers ----------------
__device__ __forceinline__ void mma16816(float& d0, float& d1, float& d2, float& d3,
                                         u32 a0, u32 a1, u32 a2, u32 a3,
                                         u32 b0, u32 b1) {
    asm volatile(
        "mma.sync.aligned.m16n8k16.row.col.f32.f16.f16.f32 "
        "{%0,%1,%2,%3}, {%4,%5,%6,%7}, {%8,%9}, {%0,%1,%2,%3};"
        : "+f"(d0), "+f"(d1), "+f"(d2), "+f"(d3)
        : "r"(a0), "r"(a1), "r"(a2), "r"(a3), "r"(b0), "r"(b1));
}
__device__ __forceinline__ u32 movm(u32 x) {
    u32 d;
    asm("movmatrix.sync.aligned.m8n8.trans.b16 %0, %1;" : "=r"(d) : "r"(x));
    return d;
}

// ---------------- global software barrier (all NBLOCKS resident) ----------
__device__ __forceinline__ void gbar(unsigned target) {
    __threadfence();          // release: make this thread's prior writes GPU-visible
    __syncthreads();
    if (threadIdx.x == 0) {
        int old = atomicAdd(&d_barcnt, 1);
        if (old == NBLOCKS - 1) {
            d_barcnt = 0;
            __threadfence();
            d_barphase = target;
        } else {
            while (d_barphase < target) __nanosleep(64);
            __threadfence();  // acquire
        }
    }
    __syncthreads();
}

// ---------------- one half-pass: out_i = num_i*numscale / sum_k M[i,k]*w16[k]
template <int TRANS>
__device__ __forceinline__ void do_pass(int strip, int lane, int warp,
                                        const unsigned char* __restrict__ tiles,
                                        const __half* __restrict__ w16,
                                        const float* __restrict__ num,
                                        float numscale,
                                        float* __restrict__ outf,
                                        __half* __restrict__ out16,
                                        float out16scale,
                                        float (*sm)[16]) {
    const u32* wp = (const u32*)w16;
    float d0a = 0, d1a = 0, d2a = 0, d3a = 0;
    float d0b = 0, d1b = 0, d2b = 0, d3b = 0;
    const int ktg = warp * 32;
    const int bl = lane & 3;

#pragma unroll 1
    for (int kk = 0; kk < 32; kk += 8) {
        u64 aw[8];
        u32 bx[8], by[8];
#pragma unroll
        for (int q = 0; q < 8; ++q) {
            int kt = ktg + kk + q;
            size_t off = TRANS ? (size_t)kt * 131072 + (size_t)strip * 256
                               : (size_t)strip * 131072 + (size_t)kt * 256;
            aw[q] = *(const u64*)(tiles + off + lane * 8);
            const u32* qb = wp + (size_t)kt * 8 + bl;
            bx[q] = qb[0];
            by[q] = qb[4];
        }
#pragma unroll
        for (int q = 0; q < 8; ++q) {
            u32 w0 = (u32)aw[q], w1 = (u32)(aw[q] >> 32);
            u32 A0 = __byte_perm(w0, 0, 0x1404) >> 2;
            u32 A1 = __byte_perm(w0, 0, 0x3424) >> 2;
            u32 A2 = __byte_perm(w1, 0, 0x1404) >> 2;
            u32 A3 = __byte_perm(w1, 0, 0x3424) >> 2;
            if (TRANS) {  // A-fragment of tile^T = {T(a0), T(a2), T(a1), T(a3)}
                u32 T0 = movm(A0), T1 = movm(A2), T2 = movm(A1), T3 = movm(A3);
                A0 = T0; A1 = T1; A2 = T2; A3 = T3;
            }
            if (q & 1) mma16816(d0b, d1b, d2b, d3b, A0, A1, A2, A3, bx[q], by[q]);
            else       mma16816(d0a, d1a, d2a, d3a, A0, A1, A2, A3, bx[q], by[q]);
        }
    }

    float s0 = d0a + d0b, s2 = d2a + d2b;
    if ((lane & 3) == 0) {            // these lanes hold D[.,0]
        sm[warp][lane >> 2] = s0;
        sm[warp][(lane >> 2) + 8] = s2;
    }
    __syncthreads();
    int t = warp * 32 + lane;
    if (t < 16) {
        float s = 0.0f;
#pragma unroll
        for (int w = 0; w < 16; ++w) s += sm[w][t];
        int row = strip * 16 + t;
        float wv = num[row] * numscale / s;
        outf[row] = wv;
        out16[row] = __float2half(wv * out16scale);
    }
}

// ---------------- persistent kernel: all 16 layers, 31 global barriers ----
__global__ void __launch_bounds__(512, 4) sinkhorn_kernel(
    const unsigned char* __restrict__ tiles,
    const float* __restrict__ alpha,
    const float* __restrict__ beta) {
    __shared__ float sm[16][16];
    const int t = threadIdx.x, lane = t & 31, warp = t >> 5;
    const int strip = blockIdx.x;
    unsigned tgt = 0;

#pragma unroll 1
    for (int l = 0; l < NLAYERS; ++l) {
        // row: u = alpha / (M v);  u16 = u * 2^25 (f16 range)
        do_pass<0>(strip, lane, warp, tiles, d_v16, alpha, 1.0f, d_u, d_u16, SIGMA_U, sm);
        gbar(++tgt);
        // col: v = beta * 2^25 / (M^T (u*2^25))
        do_pass<1>(strip, lane, warp, tiles, d_u16, beta, SIGMA_U, d_v, d_v16, 1.0f, sm);
        if (l < NLAYERS - 1) gbar(++tgt);
    }
}

// ---------------- writeout: f = eps*ln u, g = eps*ln v; reset barrier -----
__global__ void __launch_bounds__(256) writeout_kernel(float* __restrict__ out, int n,
                                                       const float* __restrict__ epsp) {
    if (blockIdx.x == 0 && threadIdx.x == 0) { d_barphase = 0; d_barcnt = 0; }
    int i = blockIdx.x * 256 + threadIdx.x;
    float eps = __ldg(epsp);
    if (i < NA) {
        if (i < n) out[i] = eps * logf(d_u[i]);
    } else if (i < NA + NB) {
        if (i < n) out[i] = eps * logf(d_v[i - NA]);
    }
}

extern "C" void kernel_launch(void* const* d_in, const int* in_sizes, int n_in,
                              void* d_out, int out_size) {
    const float* alpha = (const float*)d_in[0];
    const float* beta  = (const float*)d_in[1];
    const float* C     = (const float*)d_in[2];
    const float* eps   = (const float*)d_in[3];

    unsigned char* mPtr; cudaGetSymbolAddress((void**)&mPtr, d_M);

    encode_kernel<<<dim3(128, 128), 256>>>(C, eps);
    sinkhorn_kernel<<<NBLOCKS, 512>>>(mPtr, alpha, beta);
    writeout_kernel<<<(NA + NB + 255) / 256, 256>>>((float*)d_out, out_size, eps);
}

// round 11
// speedup vs baseline: 1.2712x; 1.2712x over previous
#include <cuda_runtime.h>
#include <cuda_fp16.h>

typedef unsigned long long u64;
typedef unsigned int u32;

#define NA 8192
#define NB 8192
#define NLAYERS 16
#define SIGMA_U 33554432.0f   // 2^25

// ---------------- static device scratch (no allocation) ----------------
__device__ __align__(128) unsigned char d_M[(size_t)NA * NB]; // A-tiled uf8, 64 MB
__device__ float d_u[NA];
__device__ float d_v[NB];
__device__ __half d_u16[NA];
__device__ __half d_v16[NB];

// ---------------- packed f32x2 helpers (encode only) ----------------
__device__ __forceinline__ u64 fma2(u64 a, u64 b, u64 c) {
    u64 d;
    asm("fma.rn.f32x2 %0,%1,%2,%3;" : "=l"(d) : "l"(a), "l"(b), "l"(c));
    return d;
}
__device__ __forceinline__ u64 add2(u64 a, u64 b) {
    u64 d;
    asm("add.rn.f32x2 %0,%1,%2;" : "=l"(d) : "l"(a), "l"(b));
    return d;
}
__device__ __forceinline__ u64 mul2(u64 a, u64 b) {
    u64 d;
    asm("mul.rn.f32x2 %0,%1,%2;" : "=l"(d) : "l"(a), "l"(b));
    return d;
}
__device__ __forceinline__ u64 pack2(float x) {
    u64 d;
    asm("mov.b64 %0, {%1, %1};" : "=l"(d) : "f"(x));
    return d;
}

#define MAG2  0x4B4000004B400000ull
#define NMAG2 0xCB400000CB400000ull
#define NONE2 0xBF800000BF800000ull

struct EC { u64 p5, p4, p3, p2, p1, p0; };
__device__ __forceinline__ EC make_ec() {
    EC e;
    e.p5 = pack2(1.33335581465e-3f);
    e.p4 = pack2(9.61812910763e-3f);
    e.p3 = pack2(5.55041086648e-2f);
    e.p2 = pack2(2.40226506959e-1f);
    e.p1 = pack2(6.93147180560e-1f);
    e.p0 = pack2(1.0f);
    return e;
}

// encode a packed pair of C values -> two uf8 bytes (b0 | b1<<8), MUFU-free.
__device__ __forceinline__ u32 enc2(u64 cpair, u64 negk2, const EC& ec) {
    u64 p = mul2(cpair, negk2);
    u64 t = add2(p, MAG2);
    u64 uu = add2(t, NMAG2);
    u64 fr = fma2(uu, NONE2, p);
    u64 r = fma2(ec.p5, fr, ec.p4);
    r = fma2(r, fr, ec.p3);
    r = fma2(r, fr, ec.p2);
    r = fma2(r, fr, ec.p1);
    r = fma2(r, fr, ec.p0);
    u32 tl = (u32)t, th = (u32)(t >> 32);
    u32 rl = (u32)r, rh = (u32)(r >> 32);
    u32 b0 = ((tl << 23) + rl + 0xC8040000u) >> 19;
    u32 b1 = ((th << 23) + rh + 0xC8040000u) >> 19;
    return b0 | (b1 << 8);
}

// ---------------- encode: C -> uf8, permuted into mma A-tiles --------------
// Tile = 16x16 uf8 (256B). Byte (lane, q) of a tile holds
//   A[lane/4 + 8*((q>>1)&1)][(lane%4)*2 + (q&1) + 8*(q>>2)]
// so one LDG.64 per lane yields mma A-fragment regs a0..a3 after (byte<<6)
// f16 expansion (uf8 bias 15 == f16 bias -> exact decode).
__global__ void __launch_bounds__(256) encode_kernel(const float* __restrict__ C,
                                                     const float* __restrict__ epsp) {
    __shared__ unsigned char sm[64][68];
    const float eps = __ldg(epsp);
    const u64 negk2 = pack2(-1.0f / (eps * 0.69314718056f));
    const EC ec = make_ec();
    const int t = threadIdx.x;
    const int i0 = blockIdx.y * 64, j0 = blockIdx.x * 64;

    {   // init v = 1
        int gid = (blockIdx.y * gridDim.x + blockIdx.x) * 256 + t;
        if (gid < NB) { d_v16[gid] = __float2half(1.0f); d_v[gid] = 1.0f; }
    }

    // load 64x64 C tile, encode to uf8 in smem
    int r = t >> 2, c0 = (t & 3) * 16;
    const float4* Crow = (const float4*)(C + (size_t)(i0 + r) * NB + j0 + c0);
    u32* srow = (u32*)&sm[r][c0];
#pragma unroll
    for (int q = 0; q < 4; ++q) {
        float4 f = Crow[q];
        u64 p0, p1;
        asm("mov.b64 %0,{%1,%2};" : "=l"(p0) : "f"(f.x), "f"(f.y));
        asm("mov.b64 %0,{%1,%2};" : "=l"(p1) : "f"(f.z), "f"(f.w));
        srow[q] = enc2(p0, negk2, ec) | (enc2(p1, negk2, ec) << 16);
    }
    __syncthreads();

    // write 16 A-subtiles (8 warps x 2 iterations)
    const int lane = t & 31, wid = t >> 5;
#pragma unroll
    for (int sub = wid; sub < 16; sub += 8) {
        int a = sub >> 2, b = sub & 3;
        u32 lo = 0, hi = 0;
#pragma unroll
        for (int q = 0; q < 8; ++q) {
            int R = (lane >> 2) + 8 * ((q >> 1) & 1);
            int k = (lane & 3) * 2 + (q & 1) + 8 * (q >> 2);
            u32 byte = sm[a * 16 + R][b * 16 + k];
            if (q < 4) lo |= byte << (8 * q); else hi |= byte << (8 * (q - 4));
        }
        size_t off = (size_t)(i0 / 16 + a) * 131072 + (size_t)(j0 / 16 + b) * 256 + lane * 8;
        *(uint2*)(d_M + off) = make_uint2(lo, hi);
    }
}

// ---------------- mma + movmatrix wrappers ----------------
__device__ __forceinline__ void mma16816(float& d0, float& d1, float& d2, float& d3,
                                         u32 a0, u32 a1, u32 a2, u32 a3,
                                         u32 b0, u32 b1) {
    asm volatile(
        "mma.sync.aligned.m16n8k16.row.col.f32.f16.f16.f32 "
        "{%0,%1,%2,%3}, {%4,%5,%6,%7}, {%8,%9}, {%0,%1,%2,%3};"
        : "+f"(d0), "+f"(d1), "+f"(d2), "+f"(d3)
        : "r"(a0), "r"(a1), "r"(a2), "r"(a3), "r"(b0), "r"(b1));
}
__device__ __forceinline__ u32 movm(u32 x) {
    u32 d;
    asm("movmatrix.sync.aligned.m8n8.trans.b16 %0, %1;" : "=r"(d) : "r"(x));
    return d;
}

// ---------------- pass: out_i = num_i * numscale / sum_k M[i,k] * w16[k] ----
// 512 threads = 16 warps; warp w covers k-tiles [w*32, w*32+32).
// The whole 16KB w16 vector is staged in smem (permuted so the B-operand
// read is one conflict-free broadcast LDS.64 per tile).
// TRANS=0: strips over rows of M (tiles contiguous).
// TRANS=1: strips over cols of M (A-fragments of M^T via movmatrix).
template <int TRANS>
__global__ void __launch_bounds__(512) pass_kernel(const unsigned char* __restrict__ tiles,
                                                   const __half* __restrict__ w16,
                                                   const float* __restrict__ num,
                                                   float numscale,
                                                   float* __restrict__ outf,
                                                   __half* __restrict__ out16,
                                                   float out16scale) {
    __shared__ __align__(16) u32 sw[4096];   // 512 tiles x 8 u32, permuted pairs
    __shared__ float sm[16][16];
    const int t = threadIdx.x;
    const int lane = t & 31, warp = t >> 5;
    const int strip = blockIdx.x;
    const u32* wp = (const u32*)w16;

    // stage w16: sw[kt*8 + 2b] = wp[kt*8 + b], sw[kt*8 + 2b + 1] = wp[kt*8 + b + 4]
#pragma unroll
    for (int idx = t; idx < 2048; idx += 512) {
        int kt = idx >> 2, b = idx & 3;
        u32 lo = wp[kt * 8 + b], hi = wp[kt * 8 + b + 4];
        *(u64*)&sw[kt * 8 + 2 * b] = (u64)lo | ((u64)hi << 32);
    }
    __syncthreads();

    float d0a = 0, d1a = 0, d2a = 0, d3a = 0;
    float d0b = 0, d1b = 0, d2b = 0, d3b = 0;
    const int ktg = warp * 32;
    const int bl = lane & 3;          // B-operand lane slot (replicated x8)

#pragma unroll 1
    for (int kk = 0; kk < 32; kk += 8) {
        u64 aw[8];
        u32 bx[8], by[8];
#pragma unroll
        for (int q = 0; q < 8; ++q) {
            int kt = ktg + kk + q;
            size_t off = TRANS ? (size_t)kt * 131072 + (size_t)strip * 256
                               : (size_t)strip * 131072 + (size_t)kt * 256;
            aw[q] = *(const u64*)(tiles + off + lane * 8);
            u64 bw = *(const u64*)&sw[kt * 8 + 2 * bl];
            bx[q] = (u32)bw;
            by[q] = (u32)(bw >> 32);
        }
#pragma unroll
        for (int q = 0; q < 8; ++q) {
            u32 w0 = (u32)aw[q], w1 = (u32)(aw[q] >> 32);
            u32 A0 = __byte_perm(w0, 0, 0x1404) >> 2;
            u32 A1 = __byte_perm(w0, 0, 0x3424) >> 2;
            u32 A2 = __byte_perm(w1, 0, 0x1404) >> 2;
            u32 A3 = __byte_perm(w1, 0, 0x3424) >> 2;
            if (TRANS) {  // A-fragment of tile^T = {T(a0), T(a2), T(a1), T(a3)}
                u32 T0 = movm(A0), T1 = movm(A2), T2 = movm(A1), T3 = movm(A3);
                A0 = T0; A1 = T1; A2 = T2; A3 = T3;
            }
            if (q & 1) mma16816(d0b, d1b, d2b, d3b, A0, A1, A2, A3, bx[q], by[q]);
            else       mma16816(d0a, d1a, d2a, d3a, A0, A1, A2, A3, bx[q], by[q]);
        }
    }

    float s0 = d0a + d0b, s2 = d2a + d2b;
    if ((lane & 3) == 0) {            // these lanes hold D[.,0]
        sm[warp][lane >> 2] = s0;
        sm[warp][(lane >> 2) + 8] = s2;
    }
    __syncthreads();
    if (t < 16) {
        float s = 0.0f;
#pragma unroll
        for (int w = 0; w < 16; ++w) s += sm[w][t];
        int row = strip * 16 + t;
        float wv = num[row] * numscale / s;
        outf[row] = wv;
        out16[row] = __float2half(wv * out16scale);
    }
}

// ---------------- writeout: f = eps*ln u, g = eps*ln v ----------------
__global__ void __launch_bounds__(256) writeout_kernel(float* __restrict__ out, int n,
                                                       const float* __restrict__ epsp) {
    int i = blockIdx.x * 256 + threadIdx.x;
    float eps = __ldg(epsp);
    if (i < NA) {
        if (i < n) out[i] = eps * logf(d_u[i]);
    } else if (i < NA + NB) {
        if (i < n) out[i] = eps * logf(d_v[i - NA]);
    }
}

extern "C" void kernel_launch(void* const* d_in, const int* in_sizes, int n_in,
                              void* d_out, int out_size) {
    const float* alpha = (const float*)d_in[0];
    const float* beta  = (const float*)d_in[1];
    const float* C     = (const float*)d_in[2];
    const float* eps   = (const float*)d_in[3];

    float* uPtr; cudaGetSymbolAddress((void**)&uPtr, d_u);
    float* vPtr; cudaGetSymbolAddress((void**)&vPtr, d_v);
    __half* u16Ptr; cudaGetSymbolAddress((void**)&u16Ptr, d_u16);
    __half* v16Ptr; cudaGetSymbolAddress((void**)&v16Ptr, d_v16);
    unsigned char* mPtr; cudaGetSymbolAddress((void**)&mPtr, d_M);

    encode_kernel<<<dim3(128, 128), 256>>>(C, eps);
    for (int l = 0; l < NLAYERS; ++l) {
        // row: u = alpha / (M v);  u16 = u * 2^25 (f16 range)
        pass_kernel<0><<<NA / 16, 512>>>(mPtr, v16Ptr, alpha, 1.0f, uPtr, u16Ptr, SIGMA_U);
        // col: v = beta * 2^25 / (M^T (u*2^25))
        pass_kernel<1><<<NB / 16, 512>>>(mPtr, u16Ptr, beta, SIGMA_U, vPtr, v16Ptr, 1.0f);
    }
    writeout_kernel<<<(NA + NB + 255) / 256, 256>>>((float*)d_out, out_size, eps);
}

// round 13
// speedup vs baseline: 1.3512x; 1.0629x over previous
#include <cuda_runtime.h>
#include <cuda_fp16.h>

typedef unsigned long long u64;
typedef unsigned int u32;

#define NA 8192
#define NB 8192
#define NLAYERS 16
#define SIGMA_U 33554432.0f   // 2^25

// ---------------- static device scratch (no allocation) ----------------
__device__ __align__(128) unsigned char d_M[(size_t)NA * NB]; // A-tiled uf8, 64 MB
__device__ float d_u[NA];
__device__ float d_v[NB];
__device__ __half d_u16[NA];
__device__ __half d_v16[NB];

// ---------------- packed f32x2 helpers (encode only) ----------------
__device__ __forceinline__ u64 fma2(u64 a, u64 b, u64 c) {
    u64 d;
    asm("fma.rn.f32x2 %0,%1,%2,%3;" : "=l"(d) : "l"(a), "l"(b), "l"(c));
    return d;
}
__device__ __forceinline__ u64 add2(u64 a, u64 b) {
    u64 d;
    asm("add.rn.f32x2 %0,%1,%2;" : "=l"(d) : "l"(a), "l"(b));
    return d;
}
__device__ __forceinline__ u64 mul2(u64 a, u64 b) {
    u64 d;
    asm("mul.rn.f32x2 %0,%1,%2;" : "=l"(d) : "l"(a), "l"(b));
    return d;
}
__device__ __forceinline__ u64 pack2(float x) {
    u64 d;
    asm("mov.b64 %0, {%1, %1};" : "=l"(d) : "f"(x));
    return d;
}

#define MAG2  0x4B4000004B400000ull
#define NMAG2 0xCB400000CB400000ull
#define NONE2 0xBF800000BF800000ull

struct EC { u64 p5, p4, p3, p2, p1, p0; };
__device__ __forceinline__ EC make_ec() {
    EC e;
    e.p5 = pack2(1.33335581465e-3f);
    e.p4 = pack2(9.61812910763e-3f);
    e.p3 = pack2(5.55041086648e-2f);
    e.p2 = pack2(2.40226506959e-1f);
    e.p1 = pack2(6.93147180560e-1f);
    e.p0 = pack2(1.0f);
    return e;
}

// encode a packed pair of C values -> two uf8 bytes (b0 | b1<<8), MUFU-free.
__device__ __forceinline__ u32 enc2(u64 cpair, u64 negk2, const EC& ec) {
    u64 p = mul2(cpair, negk2);
    u64 t = add2(p, MAG2);
    u64 uu = add2(t, NMAG2);
    u64 fr = fma2(uu, NONE2, p);
    u64 r = fma2(ec.p5, fr, ec.p4);
    r = fma2(r, fr, ec.p3);
    r = fma2(r, fr, ec.p2);
    r = fma2(r, fr, ec.p1);
    r = fma2(r, fr, ec.p0);
    u32 tl = (u32)t, th = (u32)(t >> 32);
    u32 rl = (u32)r, rh = (u32)(r >> 32);
    u32 b0 = ((tl << 23) + rl + 0xC8040000u) >> 19;
    u32 b1 = ((th << 23) + rh + 0xC8040000u) >> 19;
    return b0 | (b1 << 8);
}

// ---------------- encode: C -> uf8, permuted into mma A-tiles --------------
// Tile = 16x16 uf8 (256B). Byte (lane, q) of a tile holds
//   A[lane/4 + 8*((q>>1)&1)][(lane%4)*2 + (q&1) + 8*(q>>2)]
// so one LDG.64 per lane yields mma A-fragment regs a0..a3 after (byte<<6)
// f16 expansion (uf8 bias 15 == f16 bias -> exact decode).
__global__ void __launch_bounds__(256) encode_kernel(const float* __restrict__ C,
                                                     const float* __restrict__ epsp) {
    __shared__ unsigned char sm[64][68];
    const float eps = __ldg(epsp);
    const u64 negk2 = pack2(-1.0f / (eps * 0.69314718056f));
    const EC ec = make_ec();
    const int t = threadIdx.x;
    const int i0 = blockIdx.y * 64, j0 = blockIdx.x * 64;

    {   // init v = 1
        int gid = (blockIdx.y * gridDim.x + blockIdx.x) * 256 + t;
        if (gid < NB) { d_v16[gid] = __float2half(1.0f); d_v[gid] = 1.0f; }
    }

    // load 64x64 C tile, encode to uf8 in smem
    int r = t >> 2, c0 = (t & 3) * 16;
    const float4* Crow = (const float4*)(C + (size_t)(i0 + r) * NB + j0 + c0);
    u32* srow = (u32*)&sm[r][c0];
#pragma unroll
    for (int q = 0; q < 4; ++q) {
        float4 f = Crow[q];
        u64 p0, p1;
        asm("mov.b64 %0,{%1,%2};" : "=l"(p0) : "f"(f.x), "f"(f.y));
        asm("mov.b64 %0,{%1,%2};" : "=l"(p1) : "f"(f.z), "f"(f.w));
        srow[q] = enc2(p0, negk2, ec) | (enc2(p1, negk2, ec) << 16);
    }
    __syncthreads();

    // write 16 A-subtiles (8 warps x 2 iterations)
    const int lane = t & 31, wid = t >> 5;
#pragma unroll
    for (int sub = wid; sub < 16; sub += 8) {
        int a = sub >> 2, b = sub & 3;
        u32 lo = 0, hi = 0;
#pragma unroll
        for (int q = 0; q < 8; ++q) {
            int R = (lane >> 2) + 8 * ((q >> 1) & 1);
            int k = (lane & 3) * 2 + (q & 1) + 8 * (q >> 2);
            u32 byte = sm[a * 16 + R][b * 16 + k];
            if (q < 4) lo |= byte << (8 * q); else hi |= byte << (8 * (q - 4));
        }
        size_t off = (size_t)(i0 / 16 + a) * 131072 + (size_t)(j0 / 16 + b) * 256 + lane * 8;
        *(uint2*)(d_M + off) = make_uint2(lo, hi);
    }
}

// ---------------- mma + movmatrix wrappers ----------------
__device__ __forceinline__ void mma16816(float& d0, float& d1, float& d2, float& d3,
                                         u32 a0, u32 a1, u32 a2, u32 a3,
                                         u32 b0, u32 b1) {
    asm volatile(
        "mma.sync.aligned.m16n8k16.row.col.f32.f16.f16.f32 "
        "{%0,%1,%2,%3}, {%4,%5,%6,%7}, {%8,%9}, {%0,%1,%2,%3};"
        : "+f"(d0), "+f"(d1), "+f"(d2), "+f"(d3)
        : "r"(a0), "r"(a1), "r"(a2), "r"(a3), "r"(b0), "r"(b1));
}
__device__ __forceinline__ u32 movm(u32 x) {
    u32 d;
    asm("movmatrix.sync.aligned.m8n8.trans.b16 %0, %1;" : "=r"(d) : "r"(x));
    return d;
}

// ---------------- pass: out_i = num_i * numscale / sum_k M[i,k] * w16[k] ----
// 512 threads = 16 warps; warp w covers k-tiles [w*32, w*32+32).
// PDL: prefetch first A-tile batch (M is loop-constant -> legal pre-wait),
// griddepcontrol.wait, stage dependent 16KB w16 in smem, main loop, epilogue,
// THEN launch_dependents (so all u16/v16 writes are program-ordered before
// the signal -> visible to the next pass at its wait).
// TRANS=0: strips over rows of M (tiles contiguous).
// TRANS=1: strips over cols of M (A-fragments of M^T via movmatrix).
template <int TRANS>
__global__ void __launch_bounds__(512) pass_kernel(const unsigned char* __restrict__ tiles,
                                                   const __half* __restrict__ w16,
                                                   const float* __restrict__ num,
                                                   float numscale,
                                                   float* __restrict__ outf,
                                                   __half* __restrict__ out16,
                                                   float out16scale) {
    __shared__ __align__(16) u32 sw[4096];   // 512 tiles x 8 u32, permuted pairs
    __shared__ float sm[16][16];
    const int t = threadIdx.x;
    const int lane = t & 31, warp = t >> 5;
    const int strip = blockIdx.x;
    const u32* wp = (const u32*)w16;
    const int ktg = warp * 32;

    // prefetch first A-tile batch to L1 (M constant across passes -> race-free)
#pragma unroll
    for (int q = 0; q < 8; ++q) {
        size_t off = TRANS ? (size_t)(ktg + q) * 131072 + (size_t)strip * 256
                           : (size_t)strip * 131072 + (size_t)(ktg + q) * 256;
        asm volatile("prefetch.global.L1 [%0];" :: "l"(tiles + off + lane * 8));
    }

    // wait for the producer pass's u16/v16 writes to be visible
    asm volatile("griddepcontrol.wait;" ::: "memory");

    // stage w16: sw[kt*8 + 2b] = wp[kt*8 + b], sw[kt*8 + 2b + 1] = wp[kt*8 + b + 4]
#pragma unroll
    for (int idx = t; idx < 2048; idx += 512) {
        int kt = idx >> 2, b = idx & 3;
        u32 lo = wp[kt * 8 + b], hi = wp[kt * 8 + b + 4];
        *(u64*)&sw[kt * 8 + 2 * b] = (u64)lo | ((u64)hi << 32);
    }
    __syncthreads();

    float d0a = 0, d1a = 0, d2a = 0, d3a = 0;
    float d0b = 0, d1b = 0, d2b = 0, d3b = 0;
    const int bl = lane & 3;          // B-operand lane slot (replicated x8)

#pragma unroll 1
    for (int kk = 0; kk < 32; kk += 8) {
        u64 aw[8];
        u32 bx[8], by[8];
#pragma unroll
        for (int q = 0; q < 8; ++q) {
            int kt = ktg + kk + q;
            size_t off = TRANS ? (size_t)kt * 131072 + (size_t)strip * 256
                               : (size_t)strip * 131072 + (size_t)kt * 256;
            aw[q] = *(const u64*)(tiles + off + lane * 8);
            u64 bw = *(const u64*)&sw[kt * 8 + 2 * bl];
            bx[q] = (u32)bw;
            by[q] = (u32)(bw >> 32);
        }
#pragma unroll
        for (int q = 0; q < 8; ++q) {
            u32 w0 = (u32)aw[q], w1 = (u32)(aw[q] >> 32);
            u32 A0 = __byte_perm(w0, 0, 0x1404) >> 2;
            u32 A1 = __byte_perm(w0, 0, 0x3424) >> 2;
            u32 A2 = __byte_perm(w1, 0, 0x1404) >> 2;
            u32 A3 = __byte_perm(w1, 0, 0x3424) >> 2;
            if (TRANS) {  // A-fragment of tile^T = {T(a0), T(a2), T(a1), T(a3)}
                u32 T0 = movm(A0), T1 = movm(A2), T2 = movm(A1), T3 = movm(A3);
                A0 = T0; A1 = T1; A2 = T2; A3 = T3;
            }
            if (q & 1) mma16816(d0b, d1b, d2b, d3b, A0, A1, A2, A3, bx[q], by[q]);
            else       mma16816(d0a, d1a, d2a, d3a, A0, A1, A2, A3, bx[q], by[q]);
        }
    }

    float s0 = d0a + d0b, s2 = d2a + d2b;
    if ((lane & 3) == 0) {            // these lanes hold D[.,0]
        sm[warp][lane >> 2] = s0;
        sm[warp][(lane >> 2) + 8] = s2;
    }
    __syncthreads();
    if (t < 16) {
        float s = 0.0f;
#pragma unroll
        for (int w = 0; w < 16; ++w) s += sm[w][t];
        int row = strip * 16 + t;
        float wv = num[row] * numscale / s;
        outf[row] = wv;
        out16[row] = __float2half(wv * out16scale);
    }
    __syncthreads();   // epilogue stores are program-ordered before the signal

    // all this CTA's writes done -> allow the dependent grid to launch
    asm volatile("griddepcontrol.launch_dependents;" ::: "memory");
}

// ---------------- writeout: f = eps*ln u, g = eps*ln v ----------------
__global__ void __launch_bounds__(256) writeout_kernel(float* __restrict__ out, int n,
                                                       const float* __restrict__ epsp) {
    int i = blockIdx.x * 256 + threadIdx.x;
    float eps = __ldg(epsp);
    if (i < NA) {
        if (i < n) out[i] = eps * logf(d_u[i]);
    } else if (i < NA + NB) {
        if (i < n) out[i] = eps * logf(d_v[i - NA]);
    }
}

extern "C" void kernel_launch(void* const* d_in, const int* in_sizes, int n_in,
                              void* d_out, int out_size) {
    const float* alpha = (const float*)d_in[0];
    const float* beta  = (const float*)d_in[1];
    const float* C     = (const float*)d_in[2];
    const float* eps   = (const float*)d_in[3];

    float* uPtr; cudaGetSymbolAddress((void**)&uPtr, d_u);
    float* vPtr; cudaGetSymbolAddress((void**)&vPtr, d_v);
    __half* u16Ptr; cudaGetSymbolAddress((void**)&u16Ptr, d_u16);
    __half* v16Ptr; cudaGetSymbolAddress((void**)&v16Ptr, d_v16);
    unsigned char* mPtr; cudaGetSymbolAddress((void**)&mPtr, d_M);

    encode_kernel<<<dim3(128, 128), 256>>>(C, eps);

    cudaLaunchAttribute attrs[1];
    attrs[0].id = cudaLaunchAttributeProgrammaticStreamSerialization;
    attrs[0].val.programmaticStreamSerializationAllowed = 1;
    cudaLaunchConfig_t cfg = {};
    cfg.gridDim = dim3(NA / 16);
    cfg.blockDim = dim3(512);
    cfg.dynamicSmemBytes = 0;
    cfg.stream = 0;
    cfg.attrs = attrs;
    cfg.numAttrs = 1;

    for (int l = 0; l < NLAYERS; ++l) {
        // row: u = alpha / (M v);  u16 = u * 2^25 (f16 range)
        cudaLaunchKernelEx(&cfg, pass_kernel<0>, mPtr, (const __half*)v16Ptr,
                           alpha, 1.0f, uPtr, u16Ptr, SIGMA_U);
        // col: v = beta * 2^25 / (M^T (u*2^25))
        cudaLaunchKernelEx(&cfg, pass_kernel<1>, mPtr, (const __half*)u16Ptr,
                           beta, SIGMA_U, vPtr, v16Ptr, 1.0f);
    }
    writeout_kernel<<<(NA + NB + 255) / 256, 256>>>((float*)d_out, out_size, eps);
}

// round 16
// speedup vs baseline: 1.3553x; 1.0031x over previous
#include <cuda_runtime.h>
#include <cuda_fp16.h>

typedef unsigned long long u64;
typedef unsigned int u32;

#define NA 8192
#define NB 8192
#define NLAYERS 16
#define SIGMA_U 33554432.0f   // 2^25

// ---------------- static device scratch (no allocation) ----------------
__device__ __align__(128) unsigned char d_M[(size_t)NA * NB]; // A-tiled uf8, 64 MB
__device__ float d_u[NA];
__device__ float d_v[NB];
__device__ __half d_u16[NA];
__device__ __half d_v16[NB];

// ---------------- packed f32x2 helpers (encode only) ----------------
__device__ __forceinline__ u64 fma2(u64 a, u64 b, u64 c) {
    u64 d;
    asm("fma.rn.f32x2 %0,%1,%2,%3;" : "=l"(d) : "l"(a), "l"(b), "l"(c));
    return d;
}
__device__ __forceinline__ u64 add2(u64 a, u64 b) {
    u64 d;
    asm("add.rn.f32x2 %0,%1,%2;" : "=l"(d) : "l"(a), "l"(b));
    return d;
}
__device__ __forceinline__ u64 mul2(u64 a, u64 b) {
    u64 d;
    asm("mul.rn.f32x2 %0,%1,%2;" : "=l"(d) : "l"(a), "l"(b));
    return d;
}
__device__ __forceinline__ u64 pack2(float x) {
    u64 d;
    asm("mov.b64 %0, {%1, %1};" : "=l"(d) : "f"(x));
    return d;
}

#define MAG2  0x4B4000004B400000ull
#define NMAG2 0xCB400000CB400000ull
#define NONE2 0xBF800000BF800000ull

struct EC { u64 p5, p4, p3, p2, p1, p0; };
__device__ __forceinline__ EC make_ec() {
    EC e;
    e.p5 = pack2(1.33335581465e-3f);
    e.p4 = pack2(9.61812910763e-3f);
    e.p3 = pack2(5.55041086648e-2f);
    e.p2 = pack2(2.40226506959e-1f);
    e.p1 = pack2(6.93147180560e-1f);
    e.p0 = pack2(1.0f);
    return e;
}

// encode a packed pair of C values -> two uf8 bytes (b0 | b1<<8), MUFU-free.
__device__ __forceinline__ u32 enc2(u64 cpair, u64 negk2, const EC& ec) {
    u64 p = mul2(cpair, negk2);
    u64 t = add2(p, MAG2);
    u64 uu = add2(t, NMAG2);
    u64 fr = fma2(uu, NONE2, p);
    u64 r = fma2(ec.p5, fr, ec.p4);
    r = fma2(r, fr, ec.p3);
    r = fma2(r, fr, ec.p2);
    r = fma2(r, fr, ec.p1);
    r = fma2(r, fr, ec.p0);
    u32 tl = (u32)t, th = (u32)(t >> 32);
    u32 rl = (u32)r, rh = (u32)(r >> 32);
    u32 b0 = ((tl << 23) + rl + 0xC8040000u) >> 19;
    u32 b1 = ((th << 23) + rh + 0xC8040000u) >> 19;
    return b0 | (b1 << 8);
}

// ---------------- encode: C -> uf8, permuted into mma A-tiles --------------
// Tile = 16x16 uf8 (256B). Byte (lane, q) of a tile holds
//   A[lane/4 + 8*((q>>1)&1)][(lane%4)*2 + (q&1) + 8*(q>>2)]
// so one LDG.64 per lane yields mma A-fragment regs a0..a3 after (byte<<6)
// f16 expansion (uf8 bias 15 == f16 bias -> exact decode).
// C loads are evict-first streaming (__ldcs) so they don't evict M tiles.
__global__ void __launch_bounds__(256, 7) encode_kernel(const float* __restrict__ C,
                                                        const float* __restrict__ epsp) {
    __shared__ unsigned char sm[64][68];
    const float eps = __ldg(epsp);
    const u64 negk2 = pack2(-1.0f / (eps * 0.69314718056f));
    const EC ec = make_ec();
    const int t = threadIdx.x;
    const int i0 = blockIdx.y * 64, j0 = blockIdx.x * 64;

    {   // init v = 1
        int gid = (blockIdx.y * gridDim.x + blockIdx.x) * 256 + t;
        if (gid < NB) { d_v16[gid] = __float2half(1.0f); d_v[gid] = 1.0f; }
    }

    // load 64x64 C tile (streaming), encode to uf8 in smem
    int r = t >> 2, c0 = (t & 3) * 16;
    const ulonglong2* Crow = (const ulonglong2*)(C + (size_t)(i0 + r) * NB + j0 + c0);
    u32* srow = (u32*)&sm[r][c0];
#pragma unroll
    for (int q = 0; q < 4; ++q) {
        ulonglong2 cc = __ldcs(&Crow[q]);   // floats 4q..4q+3 as two packed pairs
        srow[q] = enc2(cc.x, negk2, ec) | (enc2(cc.y, negk2, ec) << 16);
    }
    __syncthreads();

    // write 16 A-subtiles (8 warps x 2 iterations)
    const int lane = t & 31, wid = t >> 5;
#pragma unroll
    for (int sub = wid; sub < 16; sub += 8) {
        int a = sub >> 2, b = sub & 3;
        u32 lo = 0, hi = 0;
#pragma unroll
        for (int q = 0; q < 8; ++q) {
            int R = (lane >> 2) + 8 * ((q >> 1) & 1);
            int k = (lane & 3) * 2 + (q & 1) + 8 * (q >> 2);
            u32 byte = sm[a * 16 + R][b * 16 + k];
            if (q < 4) lo |= byte << (8 * q); else hi |= byte << (8 * (q - 4));
        }
        size_t off = (size_t)(i0 / 16 + a) * 131072 + (size_t)(j0 / 16 + b) * 256 + lane * 8;
        *(uint2*)(d_M + off) = make_uint2(lo, hi);
    }
}

// ---------------- mma + movmatrix wrappers ----------------
__device__ __forceinline__ void mma16816(float& d0, float& d1, float& d2, float& d3,
                                         u32 a0, u32 a1, u32 a2, u32 a3,
                                         u32 b0, u32 b1) {
    asm volatile(
        "mma.sync.aligned.m16n8k16.row.col.f32.f16.f16.f32 "
        "{%0,%1,%2,%3}, {%4,%5,%6,%7}, {%8,%9}, {%0,%1,%2,%3};"
        : "+f"(d0), "+f"(d1), "+f"(d2), "+f"(d3)
        : "r"(a0), "r"(a1), "r"(a2), "r"(a3), "r"(b0), "r"(b1));
}
__device__ __forceinline__ u32 movm(u32 x) {
    u32 d;
    asm("movmatrix.sync.aligned.m8n8.trans.b16 %0, %1;" : "=r"(d) : "r"(x));
    return d;
}
__device__ __forceinline__ u64 ldg_nc(const unsigned char* p) {
    u64 v;
    asm("ld.global.nc.b64 %0, [%1];" : "=l"(v) : "l"(p));
    return v;
}

// ---------------- pass: out_i = num_i * numscale / sum_k M[i,k] * w16[k] ----
// 512 threads = 16 warps; warp w covers k-tiles [w*32, w*32+32).
// PDL: prefetch first A-tile batch (M is loop-constant -> legal pre-wait),
// griddepcontrol.wait, stage dependent 16KB w16 in smem, main loop, epilogue,
// THEN launch_dependents.
// TRANS=0: strips over rows of M (tiles contiguous).
// TRANS=1: strips over cols of M (A-fragments of M^T via movmatrix).
template <int TRANS>
__global__ void __launch_bounds__(512) pass_kernel(const unsigned char* __restrict__ tiles,
                                                   const __half* __restrict__ w16,
                                                   const float* __restrict__ num,
                                                   float numscale,
                                                   float* __restrict__ outf,
                                                   __half* __restrict__ out16,
                                                   float out16scale) {
    __shared__ __align__(16) u32 sw[4096];   // 512 tiles x 8 u32, permuted pairs
    __shared__ float sm[16][16];
    const int t = threadIdx.x;
    const int lane = t & 31, warp = t >> 5;
    const int strip = blockIdx.x;
    const u32* wp = (const u32*)w16;
    const int ktg = warp * 32;

    // prefetch first A-tile batch to L1 (M constant across passes -> race-free)
#pragma unroll
    for (int q = 0; q < 8; ++q) {
        size_t off = TRANS ? (size_t)(ktg + q) * 131072 + (size_t)strip * 256
                           : (size_t)strip * 131072 + (size_t)(ktg + q) * 256;
        asm volatile("prefetch.global.L1 [%0];" :: "l"(tiles + off + lane * 8));
    }

    // wait for the producer pass's u16/v16 writes to be visible
    asm volatile("griddepcontrol.wait;" ::: "memory");

    // stage w16: sw[kt*8 + 2b] = wp[kt*8 + b], sw[kt*8 + 2b + 1] = wp[kt*8 + b + 4]
#pragma unroll
    for (int idx = t; idx < 2048; idx += 512) {
        int kt = idx >> 2, b = idx & 3;
        u32 lo = wp[kt * 8 + b], hi = wp[kt * 8 + b + 4];
        *(u64*)&sw[kt * 8 + 2 * b] = (u64)lo | ((u64)hi << 32);
    }
    __syncthreads();

    float d0a = 0, d1a = 0, d2a = 0, d3a = 0;
    float d0b = 0, d1b = 0, d2b = 0, d3b = 0;
    const int bl = lane & 3;          // B-operand lane slot (replicated x8)

#pragma unroll 1
    for (int kk = 0; kk < 32; kk += 8) {
        u64 aw[8];
        u32 bx[8], by[8];
#pragma unroll
        for (int q = 0; q < 8; ++q) {
            int kt = ktg + kk + q;
            size_t off = TRANS ? (size_t)kt * 131072 + (size_t)strip * 256
                               : (size_t)strip * 131072 + (size_t)kt * 256;
            aw[q] = ldg_nc(tiles + off + lane * 8);
            u64 bw = *(const u64*)&sw[kt * 8 + 2 * bl];
            bx[q] = (u32)bw;
            by[q] = (u32)(bw >> 32);
        }
#pragma unroll
        for (int q = 0; q < 8; ++q) {
            u32 w0 = (u32)aw[q], w1 = (u32)(aw[q] >> 32);
            u32 A0 = __byte_perm(w0, 0, 0x1404) >> 2;
            u32 A1 = __byte_perm(w0, 0, 0x3424) >> 2;
            u32 A2 = __byte_perm(w1, 0, 0x1404) >> 2;
            u32 A3 = __byte_perm(w1, 0, 0x3424) >> 2;
            if (TRANS) {  // A-fragment of tile^T = {T(a0), T(a2), T(a1), T(a3)}
                u32 T0 = movm(A0), T1 = movm(A2), T2 = movm(A1), T3 = movm(A3);
                A0 = T0; A1 = T1; A2 = T2; A3 = T3;
            }
            if (q & 1) mma16816(d0b, d1b, d2b, d3b, A0, A1, A2, A3, bx[q], by[q]);
            else       mma16816(d0a, d1a, d2a, d3a, A0, A1, A2, A3, bx[q], by[q]);
        }
    }

    float s0 = d0a + d0b, s2 = d2a + d2b;
    if ((lane & 3) == 0) {            // these lanes hold D[.,0]
        sm[warp][lane >> 2] = s0;
        sm[warp][(lane >> 2) + 8] = s2;
    }
    __syncthreads();
    if (t < 16) {
        float s = 0.0f;
#pragma unroll
        for (int w = 0; w < 16; ++w) s += sm[w][t];
        int row = strip * 16 + t;
        float wv = num[row] * numscale / s;
        outf[row] = wv;
        out16[row] = __float2half(wv * out16scale);
    }
    __syncthreads();   // epilogue stores are program-ordered before the signal

    // all this CTA's writes done -> allow the dependent grid to launch
    asm volatile("griddepcontrol.launch_dependents;" ::: "memory");
}

// ---------------- writeout: f = eps*ln u, g = eps*ln v ----------------
__global__ void __launch_bounds__(256) writeout_kernel(float* __restrict__ out, int n,
                                                       const float* __restrict__ epsp) {
    asm volatile("griddepcontrol.wait;" ::: "memory");
    int i = blockIdx.x * 256 + threadIdx.x;
    float eps = __ldg(epsp);
    if (i < NA) {
        if (i < n) out[i] = eps * logf(d_u[i]);
    } else if (i < NA + NB) {
        if (i < n) out[i] = eps * logf(d_v[i - NA]);
    }
}

extern "C" void kernel_launch(void* const* d_in, const int* in_sizes, int n_in,
                              void* d_out, int out_size) {
    const float* alpha = (const float*)d_in[0];
    const float* beta  = (const float*)d_in[1];
    const float* C     = (const float*)d_in[2];
    const float* eps   = (const float*)d_in[3];

    float* uPtr; cudaGetSymbolAddress((void**)&uPtr, d_u);
    float* vPtr; cudaGetSymbolAddress((void**)&vPtr, d_v);
    __half* u16Ptr; cudaGetSymbolAddress((void**)&u16Ptr, d_u16);
    __half* v16Ptr; cudaGetSymbolAddress((void**)&v16Ptr, d_v16);
    unsigned char* mPtr; cudaGetSymbolAddress((void**)&mPtr, d_M);

    encode_kernel<<<dim3(128, 128), 256>>>(C, eps);

    cudaLaunchAttribute attrs[1];
    attrs[0].id = cudaLaunchAttributeProgrammaticStreamSerialization;
    attrs[0].val.programmaticStreamSerializationAllowed = 1;
    cudaLaunchConfig_t cfg = {};
    cfg.gridDim = dim3(NA / 16);
    cfg.blockDim = dim3(512);
    cfg.dynamicSmemBytes = 0;
    cfg.stream = 0;
    cfg.attrs = attrs;
    cfg.numAttrs = 1;

    for (int l = 0; l < NLAYERS; ++l) {
        // row: u = alpha / (M v);  u16 = u * 2^25 (f16 range)
        cudaLaunchKernelEx(&cfg, pass_kernel<0>, mPtr, (const __half*)v16Ptr,
                           alpha, 1.0f, uPtr, u16Ptr, SIGMA_U);
        // col: v = beta * 2^25 / (M^T (u*2^25))
        cudaLaunchKernelEx(&cfg, pass_kernel<1>, mPtr, (const __half*)u16Ptr,
                           beta, SIGMA_U, vPtr, v16Ptr, 1.0f);
    }

    cudaLaunchConfig_t wcfg = cfg;
    wcfg.gridDim = dim3((NA + NB + 255) / 256);
    wcfg.blockDim = dim3(256);
    cudaLaunchKernelEx(&wcfg, writeout_kernel, (float*)d_out, out_size, eps);
}